// round 17
// baseline (speedup 1.0000x reference)
#include <cuda_runtime.h>
#include <cuda_fp16.h>
#include <cstdint>

#define Sx 2048
#define Bx 2
#define Ex 512
#define Hx 8
#define Mx 2048
#define Kx 4096          // M + S
#define QKV3 1536
#define FFx 2048
#define ROWS (Sx*Bx)     // 4096
#define KB_ (Kx*Bx)      // 8192
#define EPSF 1e-5f
#define SCL 0.18033688f  // 0.125 * log2(e): folded into Q at prep time

// ---------------- scratch (static device arrays: no allocation) -------------
__device__ __align__(128) __half g_qkv[(size_t)KB_ * QKV3];
__device__ __align__(128) __half g_rb[(size_t)Kx * Ex];
__device__ __align__(128) __half g_vt[(size_t)Bx * Ex * Kx];
__device__ __align__(128) __half g_qu[(size_t)ROWS * Ex];
__device__ __align__(128) __half g_qv[(size_t)ROWS * Ex];
__device__ __align__(128) __half g_attn[(size_t)ROWS * Ex];
__device__ __align__(128) float  g_tmp[(size_t)2 * ROWS * Ex];   // 2 split-K partials
__device__ __align__(128) float  g_attnout[(size_t)ROWS * Ex];
__device__ __align__(128) __half g_attnout_h[(size_t)ROWS * Ex];
__device__ __align__(128) __half g_ff1[(size_t)ROWS * FFx];
__device__ __align__(128) float  g_ff2[(size_t)2 * ROWS * Ex];   // 2 split-K partials
__device__ __align__(128) __half g_mem_h[(size_t)Mx * Bx * Ex];
__device__ __align__(128) __half g_inp_h[(size_t)Sx * Bx * Ex];
__device__ __align__(128) __half g_pos_h[(size_t)Kx * Ex];
__device__ __align__(128) __half g_wqkv_t[(size_t)QKV3 * Ex];
__device__ __align__(128) __half g_wr_t[(size_t)Ex * Ex];
__device__ __align__(128) __half g_wo_t[(size_t)Ex * Ex];
__device__ __align__(128) __half g_w1_t[(size_t)FFx * Ex];
__device__ __align__(128) __half g_w2_t[(size_t)Ex * FFx];

// ---------------- helpers ---------------------------------------------------
__device__ __forceinline__ void mma16(float* d, const unsigned* a, const unsigned* b) {
    asm volatile(
        "mma.sync.aligned.m16n8k16.row.col.f32.f16.f16.f32 "
        "{%0,%1,%2,%3},{%4,%5,%6,%7},{%8,%9},{%0,%1,%2,%3};\n"
        : "+f"(d[0]), "+f"(d[1]), "+f"(d[2]), "+f"(d[3])
        : "r"(a[0]), "r"(a[1]), "r"(a[2]), "r"(a[3]), "r"(b[0]), "r"(b[1]));
}
__device__ __forceinline__ void ldmx4(unsigned* r, unsigned a) {
    asm volatile("ldmatrix.sync.aligned.m8n8.x4.shared.b16 {%0,%1,%2,%3}, [%4];"
        : "=r"(r[0]), "=r"(r[1]), "=r"(r[2]), "=r"(r[3]) : "r"(a));
}
__device__ __forceinline__ float ex2f(float x) {
    float r; asm("ex2.approx.f32 %0, %1;" : "=f"(r) : "f"(x)); return r;
}
__device__ __forceinline__ unsigned sptr(const void* p) {
    return (unsigned)__cvta_generic_to_shared(p);
}
__device__ __forceinline__ void cpa16(unsigned d, const void* s) {
    asm volatile("cp.async.cg.shared.global [%0], [%1], 16;\n" :: "r"(d), "l"(s));
}
__device__ __forceinline__ void cpcommit() { asm volatile("cp.async.commit_group;\n"); }
template<int N> __device__ __forceinline__ void cpwait() {
    asm volatile("cp.async.wait_group %0;\n" :: "n"(N));
}
__device__ __forceinline__ void barg(int id) {
    asm volatile("bar.sync %0, 128;" :: "r"(id) : "memory");
}
__device__ __forceinline__ unsigned packh2(float a, float b) {
    __half2 h = __floats2half2_rn(a, b);
    return *(unsigned*)&h;
}

// ---------------- fp32 -> fp16 conversion, 3 segments in one launch ---------
struct CSegs { const float4* src[3]; uint2* dst[3]; int n4[3]; };
__global__ void cvtall(CSegs segs) {
    int seg = blockIdx.y;
    int i = blockIdx.x * 256 + threadIdx.x;
    if (i < segs.n4[seg]) {
        float4 v = segs.src[seg][i];
        __half2 h01 = __floats2half2_rn(v.x, v.y);
        __half2 h23 = __floats2half2_rn(v.z, v.w);
        segs.dst[seg][i] = make_uint2(*(unsigned*)&h01, *(unsigned*)&h23);
    }
}

// ------- weight transpose + fp16 convert, ALL 5 weights, one launch ---------
struct TSegs { const float* W[5]; __half* Wt[5]; int K[5], N[5], tilesN[5], cum[6]; };
__global__ void transw_all(TSegs s) {
    int bid = blockIdx.x;
    int seg = 0;
#pragma unroll
    for (int i = 0; i < 5; i++) if (bid >= s.cum[i + 1]) seg = i + 1;
    int lt = bid - s.cum[seg];
    int K = s.K[seg], N = s.N[seg];
    int n0 = (lt % s.tilesN[seg]) * 32, k0 = (lt / s.tilesN[seg]) * 32;
    const float* W = s.W[seg];
    __half* Wt = s.Wt[seg];
    __shared__ float t[32][33];
    int tx = threadIdx.x, ty = threadIdx.y;   // 32 x 8
#pragma unroll
    for (int j = 0; j < 4; j++)
        t[ty + j * 8][tx] = W[(size_t)(k0 + ty + j * 8) * N + n0 + tx];
    __syncthreads();
#pragma unroll
    for (int j = 0; j < 4; j++)
        Wt[(size_t)(n0 + ty + j * 8) * K + k0 + tx] = __float2half_rn(t[tx][ty + j * 8]);
}

// ---------------- V transpose: vt[b*512+c][key] = qkv_V[key][b][c] ----------
__global__ void vtrans(const __half* __restrict__ qkv, __half* __restrict__ vt) {
    __shared__ __half t[32][40];
    int b = blockIdx.z;
    int key0 = blockIdx.x * 32, c0 = blockIdx.y * 32;
    int tx = threadIdx.x, ty = threadIdx.y;   // 32 x 8
#pragma unroll
    for (int j = 0; j < 4; j++)
        t[ty + j * 8][tx] =
            qkv[((size_t)(key0 + ty + j * 8) * Bx + b) * QKV3 + 1024 + c0 + tx];
    __syncthreads();
#pragma unroll
    for (int j = 0; j < 4; j++)
        vt[((size_t)(b * Ex + c0 + ty + j * 8)) * Kx + key0 + tx] = t[tx][ty + j * 8];
}

// ------- Q prep: qu/qv = fp16((q + u/v) * SCL)  (softmax scale folded in) ---
__global__ void qprep(const __half* __restrict__ qkv,
                      const float* __restrict__ u, const float* __restrict__ v,
                      __half* __restrict__ qu, __half* __restrict__ qv) {
    int row = blockIdx.x;            // s*Bx + b
    int c = threadIdx.x * 2;         // 256 threads x 2 halfs
    __half2 q = *(const __half2*)(qkv + ((size_t)(Mx * Bx) + row) * QKV3 + c);
    float qx = __half2float(q.x), qy = __half2float(q.y);
    float2 uu = *(const float2*)(u + c);
    float2 vv = *(const float2*)(v + c);
    *(__half2*)(qu + (size_t)row * Ex + c) =
        __floats2half2_rn((qx + uu.x) * SCL, (qy + uu.y) * SCL);
    *(__half2*)(qv + (size_t)row * Ex + c) =
        __floats2half2_rn((qx + vv.x) * SCL, (qy + vv.y) * SCL);
}

// ------- FP16 GEMM: C(MxN)=A(MxK)*Bt(NxK)^T, 128x128x32, 4-stage pipe ------
#define AH 40
#define GSTG 4
#define GBUF (128*AH*2)          // bytes per operand per stage
#define GEMM_SMEM (2*GSTG*GBUF)  // A stages + B stages

template<int EPI, bool SPLITA, bool OUTH>
__global__ __launch_bounds__(256, 2) void tgemm(
    const __half* __restrict__ A0, const __half* __restrict__ A1, int splitRow,
    const __half* __restrict__ Bt, const float* __restrict__ bias,
    void* __restrict__ Cv, int Nd, int Kd, int kLen, size_t coffBytes)
{
    extern __shared__ __align__(16) __half sh[];
    __half* As = sh;                      // [GSTG][128][AH]
    __half* Bs = sh + GSTG * 128 * AH;    // [GSTG][128][AH]
    const int tid = threadIdx.x, lane = tid & 31, wid = tid >> 5;
    const int wm = wid >> 2, wn = wid & 3, g = lane >> 2, t = lane & 3;
    const int bm = blockIdx.y * 128, bn = blockIdx.x * 128;
    const int kOff = blockIdx.z * kLen;
    const bool bz0 = (blockIdx.z == 0);
    char* Cb = (char*)Cv + (size_t)blockIdx.z * coffBytes;

    const __half* asrc[2]; const __half* bsrc[2];
    unsigned adst[2], bdst[2];
#pragma unroll
    for (int p = 0; p < 2; p++) {
        int id = tid + p * 256;
        int r = id >> 2, c8 = (id & 3) * 8;
        int grow = bm + r;
        const __half* abase = (SPLITA && grow >= splitRow)
                              ? (A1 + (size_t)(grow - splitRow) * Kd)
                              : (A0 + (size_t)grow * Kd);
        asrc[p] = abase + kOff + c8;
        adst[p] = sptr(As + r * AH + c8);
        bsrc[p] = Bt + (size_t)(bn + r) * Kd + kOff + c8;
        bdst[p] = sptr(Bs + r * AH + c8);
    }

    const int r_in = lane & 7;
    const int a_row8 = ((lane >> 3) & 1) * 8;
    const int a_k8 = (lane >> 4) * 8;
    const int b_nf8 = (lane >> 4) * 8;
    const int b_k8 = ((lane >> 3) & 1) * 8;
    const unsigned aAddr0 = sptr(As + (wm * 64 + r_in + a_row8) * AH + a_k8);
    const unsigned bAddr0 = sptr(Bs + (wn * 32 + b_nf8 + r_in) * AH + b_k8);

    float acc[4][4][4];
#pragma unroll
    for (int i = 0; i < 4; i++)
#pragma unroll
        for (int j = 0; j < 4; j++)
#pragma unroll
            for (int r = 0; r < 4; r++) acc[i][j][r] = 0.f;

    auto issue = [&](int stage) {
        unsigned off = (unsigned)(stage % GSTG) * GBUF;
        int k0 = stage << 5;
#pragma unroll
        for (int p = 0; p < 2; p++) {
            cpa16(adst[p] + off, asrc[p] + k0);
            cpa16(bdst[p] + off, bsrc[p] + k0);
        }
        cpcommit();
    };

    int nkt = kLen >> 5;   // >= 8 for all our shapes
#pragma unroll
    for (int s = 0; s < GSTG - 1; s++) issue(s);

    for (int kt = 0; kt < nkt; kt++) {
        cpwait<GSTG - 2>();
        __syncthreads();
        if (kt + GSTG - 1 < nkt) issue(kt + GSTG - 1);

        unsigned off = (unsigned)(kt % GSTG) * GBUF;
        unsigned aAddr = aAddr0 + off;
        unsigned bAddr = bAddr0 + off;
#pragma unroll
        for (int ks = 0; ks < 2; ks++) {
            unsigned a4[4][4], b4[2][4];
#pragma unroll
            for (int mf = 0; mf < 4; mf++)
                ldmx4(a4[mf], aAddr + mf * (16 * AH * 2) + ks * 32);
#pragma unroll
            for (int n2 = 0; n2 < 2; n2++)
                ldmx4(b4[n2], bAddr + n2 * (16 * AH * 2) + ks * 32);
#pragma unroll
            for (int mf = 0; mf < 4; mf++)
#pragma unroll
                for (int n2 = 0; n2 < 2; n2++) {
                    mma16(acc[mf][2 * n2],     a4[mf], b4[n2]);
                    mma16(acc[mf][2 * n2 + 1], a4[mf], b4[n2] + 2);
                }
        }
    }

#pragma unroll
    for (int mf = 0; mf < 4; mf++) {
        int r0 = bm + wm * 64 + mf * 16 + g;
#pragma unroll
        for (int nf = 0; nf < 4; nf++) {
            int c = bn + wn * 32 + nf * 8 + 2 * t;
            float v0 = acc[mf][nf][0], v1 = acc[mf][nf][1];
            float v2 = acc[mf][nf][2], v3 = acc[mf][nf][3];
            if (EPI >= 1 && bz0) {
                float b0 = bias[c], b1v = bias[c + 1];
                v0 += b0; v1 += b1v; v2 += b0; v3 += b1v;
            }
            if (EPI == 2) {
                v0 = fmaxf(v0, 0.f); v1 = fmaxf(v1, 0.f);
                v2 = fmaxf(v2, 0.f); v3 = fmaxf(v3, 0.f);
            }
            if (OUTH) {
                __half* C = (__half*)Cb;
                *(__half2*)(C + (size_t)r0 * Nd + c)       = __floats2half2_rn(v0, v1);
                *(__half2*)(C + (size_t)(r0 + 8) * Nd + c) = __floats2half2_rn(v2, v3);
            } else {
                float* C = (float*)Cb;
                *(float2*)(C + (size_t)r0 * Nd + c)       = make_float2(v0, v1);
                *(float2*)(C + (size_t)(r0 + 8) * Nd + c) = make_float2(v2, v3);
            }
        }
    }
}

// ---------------- Flash attention: joint 2-tile (128-key) softmax -----------
#define FST 72
#define BDW 84
#define OFF_QU 0
#define OFF_QV 9216
#define OFF_K  18432
#define OFF_V  55296
#define OFF_R  92160
#define OFF_BD 165888
#define FLASH_SMEM 208896
#define PRSTRIDE 2304      // 16 * FST * 2 bytes
#define KSTB 9216          // bytes per K/V stage buffer
#define RSTB 18432         // bytes per R stage buffer

__global__ __launch_bounds__(256, 1) void flash(
    const __half* __restrict__ qkv, const __half* __restrict__ rbuf,
    const __half* __restrict__ vt,
    const __half* __restrict__ qu_g, const __half* __restrict__ qv_g,
    __half* __restrict__ attn)
{
    extern __shared__ __align__(16) char smc[];
    __half* Qu = (__half*)(smc + OFF_QU);
    __half* Qv = (__half*)(smc + OFF_QV);
    __half* Ks = (__half*)(smc + OFF_K);
    __half* Vs = (__half*)(smc + OFF_V);
    __half* Rs = (__half*)(smc + OFF_R);
    float*  BDb = (float*)(smc + OFF_BD);
    const int tid = threadIdx.x, lane = tid & 31, wid = tid >> 5;
    const int g = lane >> 2, t = lane & 3;
    const int gr = wid >> 2, wg = wid & 3;
    const int gtid = tid & 127;
    const int qt = (gridDim.x - 1) - blockIdx.x;
    const int b = blockIdx.y >> 3, h = blockIdx.y & 7;
    const int s0 = qt * 64, hoff = h * 64;
    const int nkt = qt + 33;

    auto issue = [&](int kt, int st) {
        int k0 = kt * 64;
        int slot = gr * 2 + st;
#pragma unroll
        for (int p = 0; p < 4; p++) {
            int id = gtid + p * 128;
            int row = id >> 3, c = (id & 7) * 8;
            const __half* ksrc = qkv + ((size_t)(k0 + row) * Bx + b) * QKV3 + 512 + hoff + c;
            cpa16(sptr(Ks + slot * 64 * FST + row * FST + c), ksrc);
            cpa16(sptr(Vs + slot * 64 * FST + row * FST + c),
                  vt + ((size_t)(b * Ex + hoff + row)) * Kx + k0 + c);
        }
        int jlo = k0 + (Sx - 1) - s0 - 63;
#pragma unroll
        for (int p = 0; p < 8; p++) {
            int id = gtid + p * 128;
            int d = id >> 3, c = (id & 7) * 8;
            int j = jlo + d; if (j > Kx - 1) j = Kx - 1;   // clamped cells are masked
            cpa16(sptr(Rs + slot * 128 * FST + d * FST + c), rbuf + (size_t)j * Ex + hoff + c);
        }
        cpcommit();
    };

    // Q tiles via cp.async, then per-group stage prefetches
#pragma unroll
    for (int p = 0; p < 2; p++) {
        int id = tid + p * 256;
        int row = id >> 3, c = (id & 7) * 8;
        size_t src = ((size_t)(s0 + row) * Bx + b) * Ex + hoff + c;
        cpa16(sptr(Qu + row * FST + c), qu_g + src);
        cpa16(sptr(Qv + row * FST + c), qv_g + src);
    }
    cpcommit();
    issue(gr, 0);
    issue(gr + 2, 1);    // nkt >= 33 always
    cpwait<2>();         // retire Q group
    __syncthreads();

    float m0 = -1e30f, m1 = -1e30f, l0 = 0.f, l1 = 0.f;
    float O[8][4];
#pragma unroll
    for (int i = 0; i < 8; i++)
#pragma unroll
        for (int j = 0; j < 4; j++) O[i][j] = 0.f;

    float* BDrow = BDb + (wid * 16 + g) * BDW;
    const int c_base = 48 - wg * 16;
    const int limg = s0 + wg * 16 + Mx;   // min row limit in this warp

    const int r_in = lane & 7;
    const int a_row8 = ((lane >> 3) & 1) * 8;
    const int a_k8 = (lane >> 4) * 8;
    const int b_nf8 = (lane >> 4) * 8;
    const int b_k8 = ((lane >> 3) & 1) * 8;
    const unsigned qu_a = sptr(Qu + (wg * 16 + r_in + a_row8) * FST + a_k8);
    const unsigned qv_a = sptr(Qv + (wg * 16 + r_in + a_row8) * FST + a_k8);
    const unsigned k_b0 = sptr(Ks + (gr * 2) * 64 * FST + (b_nf8 + r_in) * FST + b_k8);
    const unsigned r_b0 = sptr(Rs + (gr * 2) * 128 * FST + (c_base + b_nf8 + r_in) * FST + b_k8);
    const unsigned v_b0 = sptr(Vs + (gr * 2) * 64 * FST + (b_nf8 + r_in) * FST + b_k8);

    auto do_tile = [&](unsigned k_b, unsigned r_b, float (*ac)[4]) {
        float bd[10][4];
#pragma unroll
        for (int nf = 0; nf < 10; nf++)
#pragma unroll
            for (int j = 0; j < 4; j++) bd[nf][j] = 0.f;
#pragma unroll
        for (int ks = 0; ks < 4; ks++) {
            unsigned a[4];
            ldmx4(a, qv_a + ks * 32);
#pragma unroll
            for (int pr = 0; pr < 5; pr++) {
                unsigned bb[4];
                ldmx4(bb, r_b + pr * PRSTRIDE + ks * 32);
                mma16(bd[2 * pr],     a, bb);
                mma16(bd[2 * pr + 1], a, bb + 2);
            }
        }
#pragma unroll
        for (int nf = 0; nf < 10; nf++) {
            *(float2*)(BDrow + nf * 8 + 2 * t) = make_float2(bd[nf][0], bd[nf][1]);
            *(float2*)(BDrow + 8 * BDW + nf * 8 + 2 * t) = make_float2(bd[nf][2], bd[nf][3]);
        }
        __syncwarp();
#pragma unroll
        for (int nf = 0; nf < 8; nf++) {
            int kc = nf * 8 + 2 * t;
            ac[nf][0] = BDrow[kc + 15 - g];
            ac[nf][1] = BDrow[kc + 16 - g];
            ac[nf][2] = BDrow[8 * BDW + kc + 7 - g];
            ac[nf][3] = BDrow[8 * BDW + kc + 8 - g];
        }
#pragma unroll
        for (int ks = 0; ks < 4; ks++) {
            unsigned a[4];
            ldmx4(a, qu_a + ks * 32);
#pragma unroll
            for (int pr = 0; pr < 4; pr++) {
                unsigned bb[4];
                ldmx4(bb, k_b + pr * PRSTRIDE + ks * 32);
                mma16(ac[2 * pr],     a, bb);
                mma16(ac[2 * pr + 1], a, bb + 2);
            }
        }
        __syncwarp();   // seed LDS ordered before next tile's BD stores
    };

    auto do_pv = [&](unsigned v_b, const unsigned* p0, const unsigned* p1) {
#pragma unroll
        for (int ks = 0; ks < 4; ks++) {
            unsigned a[4] = {p0[2 * ks], p1[2 * ks], p0[2 * ks + 1], p1[2 * ks + 1]};
#pragma unroll
            for (int pr = 0; pr < 4; pr++) {
                unsigned bb[4];
                ldmx4(bb, v_b + pr * PRSTRIDE + ks * 32);
                mma16(O[2 * pr],     a, bb);
                mma16(O[2 * pr + 1], a, bb + 2);
            }
        }
    };

    auto mask_tile = [&](int k0, float (*ac)[4]) {
        int lim0 = limg + g, lim1 = lim0 + 8;
#pragma unroll
        for (int nf = 0; nf < 8; nf++) {
            int kc = nf * 8 + 2 * t;
            if (k0 + kc > lim0)     ac[nf][0] = -1e30f;
            if (k0 + kc + 1 > lim0) ac[nf][1] = -1e30f;
            if (k0 + kc > lim1)     ac[nf][2] = -1e30f;
            if (k0 + kc + 1 > lim1) ac[nf][3] = -1e30f;
        }
    };

    int kt = gr;
    for (; kt + 2 < nkt; kt += 4) {        // joint pair (kt, kt+2)
        int k0A = kt * 64, k0B = k0A + 128;
        cpwait<0>();
        barg(gr + 1);

        float acA[8][4], acB[8][4];
        do_tile(k_b0, r_b0, acA);
        do_tile(k_b0 + KSTB, r_b0 + RSTB, acB);

        if (k0B + 63 > limg) { mask_tile(k0A, acA); mask_tile(k0B, acB); }

        // ---- joint softmax over 128 keys
        unsigned pA0[8], pA1[8], pB0[8], pB1[8];
        {
            float mx0 = -1e30f, mx1 = -1e30f;
#pragma unroll
            for (int nf = 0; nf < 8; nf++) {
                mx0 = fmaxf(mx0, fmaxf(fmaxf(acA[nf][0], acA[nf][1]),
                                       fmaxf(acB[nf][0], acB[nf][1])));
                mx1 = fmaxf(mx1, fmaxf(fmaxf(acA[nf][2], acA[nf][3]),
                                       fmaxf(acB[nf][2], acB[nf][3])));
            }
            mx0 = fmaxf(mx0, __shfl_xor_sync(0xffffffffu, mx0, 1));
            mx0 = fmaxf(mx0, __shfl_xor_sync(0xffffffffu, mx0, 2));
            mx1 = fmaxf(mx1, __shfl_xor_sync(0xffffffffu, mx1, 1));
            mx1 = fmaxf(mx1, __shfl_xor_sync(0xffffffffu, mx1, 2));
            float mn0 = fmaxf(m0, mx0), mn1 = fmaxf(m1, mx1);
            float c0 = ex2f(m0 - mn0), c1 = ex2f(m1 - mn1);
            float rs0 = 0.f, rs1 = 0.f;
#pragma unroll
            for (int nf = 0; nf < 8; nf++) {
                float a0 = ex2f(acA[nf][0] - mn0), a1 = ex2f(acA[nf][1] - mn0);
                float a2 = ex2f(acA[nf][2] - mn1), a3 = ex2f(acA[nf][3] - mn1);
                float b0v = ex2f(acB[nf][0] - mn0), b1v = ex2f(acB[nf][1] - mn0);
                float b2v = ex2f(acB[nf][2] - mn1), b3v = ex2f(acB[nf][3] - mn1);
                rs0 += a0 + a1 + b0v + b1v;
                rs1 += a2 + a3 + b2v + b3v;
                pA0[nf] = packh2(a0, a1); pA1[nf] = packh2(a2, a3);
                pB0[nf] = packh2(b0v, b1v); pB1[nf] = packh2(b2v, b3v);
            }
            rs0 += __shfl_xor_sync(0xffffffffu, rs0, 1);
            rs0 += __shfl_xor_sync(0xffffffffu, rs0, 2);
            rs1 += __shfl_xor_sync(0xffffffffu, rs1, 1);
            rs1 += __shfl_xor_sync(0xffffffffu, rs1, 2);
            l0 = l0 * c0 + rs0; l1 = l1 * c1 + rs1;
            m0 = mn0; m1 = mn1;
#pragma unroll
            for (int nf = 0; nf < 8; nf++) {
                O[nf][0] *= c0; O[nf][1] *= c0; O[nf][2] *= c1; O[nf][3] *= c1;
            }
        }

        do_pv(v_b0, pA0, pA1);
        do_pv(v_b0 + KSTB, pB0, pB1);

        barg(gr + 1);
        if (kt + 4 < nkt) issue(kt + 4, 0);
        if (kt + 6 < nkt) issue(kt + 6, 1);
    }

    if (kt < nkt) {   // single tail tile (stage 0)
        int k0 = kt * 64;
        cpwait<0>();
        barg(gr + 1);

        float ac[8][4];
        do_tile(k_b0, r_b0, ac);
        if (k0 + 63 > limg) mask_tile(k0, ac);

        unsigned p0[8], p1[8];
        {
            float mx0 = -1e30f, mx1 = -1e30f;
#pragma unroll
            for (int nf = 0; nf < 8; nf++) {
                mx0 = fmaxf(mx0, fmaxf(ac[nf][0], ac[nf][1]));
                mx1 = fmaxf(mx1, fmaxf(ac[nf][2], ac[nf][3]));
            }
            mx0 = fmaxf(mx0, __shfl_xor_sync(0xffffffffu, mx0, 1));
            mx0 = fmaxf(mx0, __shfl_xor_sync(0xffffffffu, mx0, 2));
            mx1 = fmaxf(mx1, __shfl_xor_sync(0xffffffffu, mx1, 1));
            mx1 = fmaxf(mx1, __shfl_xor_sync(0xffffffffu, mx1, 2));
            float mn0 = fmaxf(m0, mx0), mn1 = fmaxf(m1, mx1);
            float c0 = ex2f(m0 - mn0), c1 = ex2f(m1 - mn1);
            float rs0 = 0.f, rs1 = 0.f;
#pragma unroll
            for (int nf = 0; nf < 8; nf++) {
                float a0 = ex2f(ac[nf][0] - mn0), a1 = ex2f(ac[nf][1] - mn0);
                float a2 = ex2f(ac[nf][2] - mn1), a3 = ex2f(ac[nf][3] - mn1);
                rs0 += a0 + a1; rs1 += a2 + a3;
                p0[nf] = packh2(a0, a1); p1[nf] = packh2(a2, a3);
            }
            rs0 += __shfl_xor_sync(0xffffffffu, rs0, 1);
            rs0 += __shfl_xor_sync(0xffffffffu, rs0, 2);
            rs1 += __shfl_xor_sync(0xffffffffu, rs1, 1);
            rs1 += __shfl_xor_sync(0xffffffffu, rs1, 2);
            l0 = l0 * c0 + rs0; l1 = l1 * c1 + rs1;
            m0 = mn0; m1 = mn1;
#pragma unroll
            for (int nf = 0; nf < 8; nf++) {
                O[nf][0] *= c0; O[nf][1] *= c0; O[nf][2] *= c1; O[nf][3] *= c1;
            }
        }
        do_pv(v_b0, p0, p1);
        barg(gr + 1);
    }

    // ---- merge the two groups' partial softmax states, write output --------
    __syncthreads();
    if (wid >= 4) {
#pragma unroll
        for (int nf = 0; nf < 8; nf++) {
            *(float2*)(BDrow + nf * 8 + 2 * t) = make_float2(O[nf][0], O[nf][1]);
            *(float2*)(BDrow + 8 * BDW + nf * 8 + 2 * t) = make_float2(O[nf][2], O[nf][3]);
        }
        if (t == 0) {
            BDrow[80] = m0; BDrow[81] = l0;
            BDrow[8 * BDW + 80] = m1; BDrow[8 * BDW + 81] = l1;
        }
    }
    __syncthreads();
    if (wid < 4) {
        const float* Peer = BDb + ((wid + 4) * 16 + g) * BDW;
        float pm0 = Peer[80], pl0 = Peer[81];
        float pm1 = Peer[8 * BDW + 80], pl1 = Peer[8 * BDW + 81];
        float M0 = fmaxf(m0, pm0), M1 = fmaxf(m1, pm1);
        float a0 = ex2f(m0 - M0), e0 = ex2f(pm0 - M0);
        float a1 = ex2f(m1 - M1), e1 = ex2f(pm1 - M1);
        float i0 = 1.0f / (l0 * a0 + pl0 * e0);
        float i1 = 1.0f / (l1 * a1 + pl1 * e1);
        int sg0 = s0 + wid * 16 + g;
#pragma unroll
        for (int nf = 0; nf < 8; nf++) {
            int c = hoff + nf * 8 + 2 * t;
            float2 po0 = *(const float2*)(Peer + nf * 8 + 2 * t);
            float2 po1 = *(const float2*)(Peer + 8 * BDW + nf * 8 + 2 * t);
            *(__half2*)(attn + ((size_t)sg0 * Bx + b) * Ex + c) =
                __floats2half2_rn((O[nf][0] * a0 + po0.x * e0) * i0,
                                  (O[nf][1] * a0 + po0.y * e0) * i0);
            *(__half2*)(attn + ((size_t)(sg0 + 8) * Bx + b) * Ex + c) =
                __floats2half2_rn((O[nf][2] * a1 + po1.x * e1) * i1,
                                  (O[nf][3] * a1 + po1.y * e1) * i1);
        }
    }
}

// -------- LayerNorm(X + Y [+ Y2]); optional fp16 second copy ----------------
__global__ void ln_add_kernel(const float* __restrict__ X, const float* __restrict__ Y,
                              const float* __restrict__ Y2,
                              const float* __restrict__ g, const float* __restrict__ bb,
                              float* __restrict__ out, __half* __restrict__ out_h)
{
    __shared__ float red[4];
    int row = blockIdx.x;
    int tid = threadIdx.x;
    const float4* X4 = (const float4*)(X + (size_t)row * Ex);
    const float4* Y4 = (const float4*)(Y + (size_t)row * Ex);
    float4 x = X4[tid], y = Y4[tid];
    float4 vv = {x.x + y.x, x.y + y.y, x.z + y.z, x.w + y.w};
    if (Y2) {
        float4 y2 = ((const float4*)(Y2 + (size_t)row * Ex))[tid];
        vv.x += y2.x; vv.y += y2.y; vv.z += y2.z; vv.w += y2.w;
    }
    float s = vv.x + vv.y + vv.z + vv.w;
#pragma unroll
    for (int off = 16; off; off >>= 1) s += __shfl_xor_sync(0xffffffffu, s, off);
    if ((tid & 31) == 0) red[tid >> 5] = s;
    __syncthreads();
    float mu = (red[0] + red[1] + red[2] + red[3]) * (1.f / 512.f);
    float d0 = vv.x - mu, d1 = vv.y - mu, d2 = vv.z - mu, d3 = vv.w - mu;
    float q = d0 * d0 + d1 * d1 + d2 * d2 + d3 * d3;
    __syncthreads();
#pragma unroll
    for (int off = 16; off; off >>= 1) q += __shfl_xor_sync(0xffffffffu, q, off);
    if ((tid & 31) == 0) red[tid >> 5] = q;
    __syncthreads();
    float var = (red[0] + red[1] + red[2] + red[3]) * (1.f / 512.f);
    float rs = rsqrtf(var + EPSF);
    float4 gg = ((const float4*)g)[tid], bv = ((const float4*)bb)[tid];
    float4 o;
    o.x = d0 * rs * gg.x + bv.x;
    o.y = d1 * rs * gg.y + bv.y;
    o.z = d2 * rs * gg.z + bv.z;
    o.w = d3 * rs * gg.w + bv.w;
    ((float4*)(out + (size_t)row * Ex))[tid] = o;
    if (out_h) {
        __half2* oh = (__half2*)(out_h + (size_t)row * Ex);
        oh[tid * 2]     = __floats2half2_rn(o.x, o.y);
        oh[tid * 2 + 1] = __floats2half2_rn(o.z, o.w);
    }
}

// ---------------------------------------------------------------------------
extern "C" void kernel_launch(void* const* d_in, const int* in_sizes, int n_in,
                              void* d_out, int out_size)
{
    const float* inputDec = (const float*)d_in[0];
    const float* posEmb   = (const float*)d_in[1];
    const float* u        = (const float*)d_in[2];
    const float* v        = (const float*)d_in[3];
    const float* memories = (const float*)d_in[4];
    const float* Wqkv     = (const float*)d_in[5];
    const float* Wr       = (const float*)d_in[6];
    const float* Wo       = (const float*)d_in[7];
    const float* ln1_g    = (const float*)d_in[8];
    const float* ln1_b    = (const float*)d_in[9];
    const float* W1       = (const float*)d_in[10];
    const float* b1       = (const float*)d_in[11];
    const float* W2       = (const float*)d_in[12];
    const float* b2       = (const float*)d_in[13];
    const float* ln2_g    = (const float*)d_in[14];
    const float* ln2_b    = (const float*)d_in[15];
    float* out = (float*)d_out;

    __half *qkv, *rb, *vt, *qu, *qv, *attn, *attnout_h, *ff1;
    __half *mem_h, *inp_h, *pos_h, *wqkv_t, *wr_t, *wo_t, *w1_t, *w2_t;
    float *tmp, *attnout, *ff2;
    cudaGetSymbolAddress((void**)&qkv,       g_qkv);
    cudaGetSymbolAddress((void**)&rb,        g_rb);
    cudaGetSymbolAddress((void**)&vt,        g_vt);
    cudaGetSymbolAddress((void**)&qu,        g_qu);
    cudaGetSymbolAddress((void**)&qv,        g_qv);
    cudaGetSymbolAddress((void**)&attn,      g_attn);
    cudaGetSymbolAddress((void**)&tmp,       g_tmp);
    cudaGetSymbolAddress((void**)&attnout,   g_attnout);
    cudaGetSymbolAddress((void**)&attnout_h, g_attnout_h);
    cudaGetSymbolAddress((void**)&ff1,       g_ff1);
    cudaGetSymbolAddress((void**)&ff2,       g_ff2);
    cudaGetSymbolAddress((void**)&mem_h,     g_mem_h);
    cudaGetSymbolAddress((void**)&inp_h,     g_inp_h);
    cudaGetSymbolAddress((void**)&pos_h,     g_pos_h);
    cudaGetSymbolAddress((void**)&wqkv_t,    g_wqkv_t);
    cudaGetSymbolAddress((void**)&wr_t,      g_wr_t);
    cudaGetSymbolAddress((void**)&wo_t,      g_wo_t);
    cudaGetSymbolAddress((void**)&w1_t,      g_w1_t);
    cudaGetSymbolAddress((void**)&w2_t,      g_w2_t);

    cudaFuncSetAttribute(flash, cudaFuncAttributeMaxDynamicSharedMemorySize, FLASH_SMEM);
    cudaFuncSetAttribute(tgemm<0,true,true>,   cudaFuncAttributeMaxDynamicSharedMemorySize, GEMM_SMEM);
    cudaFuncSetAttribute(tgemm<0,false,true>,  cudaFuncAttributeMaxDynamicSharedMemorySize, GEMM_SMEM);
    cudaFuncSetAttribute(tgemm<0,false,false>, cudaFuncAttributeMaxDynamicSharedMemorySize, GEMM_SMEM);
    cudaFuncSetAttribute(tgemm<2,false,true>,  cudaFuncAttributeMaxDynamicSharedMemorySize, GEMM_SMEM);
    cudaFuncSetAttribute(tgemm<1,false,false>, cudaFuncAttributeMaxDynamicSharedMemorySize, GEMM_SMEM);

    // 0a) activations fp32 -> fp16
    {
        CSegs cs;
        cs.src[0] = (const float4*)memories; cs.dst[0] = (uint2*)mem_h;
        cs.n4[0] = (int)((size_t)Mx * Bx * Ex / 4);
        cs.src[1] = (const float4*)inputDec; cs.dst[1] = (uint2*)inp_h;
        cs.n4[1] = (int)((size_t)Sx * Bx * Ex / 4);
        cs.src[2] = (const float4*)posEmb;   cs.dst[2] = (uint2*)pos_h;
        cs.n4[2] = (int)((size_t)Kx * Ex / 4);
        int maxb = 0;
        for (int i = 0; i < 3; i++) { int bl = (cs.n4[i] + 255) / 256; if (bl > maxb) maxb = bl; }
        cvtall<<<dim3(maxb, 3), 256>>>(cs);
    }
    // 0b) all 5 weight transposes in ONE launch
    {
        TSegs ts;
        const float* Ws[5] = {Wqkv, Wr, Wo, W1, W2};
        __half* Wts[5] = {wqkv_t, wr_t, wo_t, w1_t, w2_t};
        int Ks[5] = {Ex, Ex, Ex, Ex, FFx};
        int Ns[5] = {QKV3, Ex, Ex, FFx, Ex};
        int c = 0;
        ts.cum[0] = 0;
        for (int i = 0; i < 5; i++) {
            ts.W[i] = Ws[i]; ts.Wt[i] = Wts[i];
            ts.K[i] = Ks[i]; ts.N[i] = Ns[i];
            ts.tilesN[i] = Ns[i] / 32;
            c += (Ks[i] / 32) * (Ns[i] / 32);
            ts.cum[i + 1] = c;
        }
        transw_all<<<c, dim3(32, 8)>>>(ts);
    }

    const size_t HALF_OUT = (size_t)ROWS * Ex * sizeof(float);

    // 1) qkv GEMM
    tgemm<0,true,true><<<dim3(QKV3/128, KB_/128, 1), 256, GEMM_SMEM>>>(
        mem_h, inp_h, Mx * Bx, wqkv_t, nullptr, qkv, QKV3, Ex, Ex, 0);
    // 2) r GEMM
    tgemm<0,false,true><<<dim3(Ex/128, Kx/128, 1), 256, GEMM_SMEM>>>(
        pos_h, nullptr, 0, wr_t, nullptr, rb, Ex, Ex, Ex, 0);
    // 2b) V transpose + Q prep
    vtrans<<<dim3(Kx/32, Ex/32, Bx), dim3(32,8)>>>(qkv, vt);
    qprep<<<ROWS, 256>>>(qkv, u, v, qu, qv);
    // 3) flash attention (joint 2-tile softmax)
    flash<<<dim3(Sx/64, Bx*Hx), 256, FLASH_SMEM>>>(qkv, rb, vt, qu, qv, attn);
    // 4) attn @ Wo  (split-K x2)
    tgemm<0,false,false><<<dim3(Ex/128, ROWS/128, 2), 256, GEMM_SMEM>>>(
        attn, nullptr, 0, wo_t, nullptr, tmp, Ex, Ex, Ex/2, HALF_OUT);
    // 5) attn_out = LN(inputDec + woA + woB)
    ln_add_kernel<<<ROWS, 128>>>(inputDec, tmp, tmp + (size_t)ROWS * Ex,
                                 ln1_g, ln1_b, attnout, attnout_h);
    // 6) ff1 = relu(attn_out @ W1 + b1)
    tgemm<2,false,true><<<dim3(FFx/128, ROWS/128, 1), 256, GEMM_SMEM>>>(
        attnout_h, nullptr, 0, w1_t, b1, ff1, FFx, Ex, Ex, 0);
    // 7) ff2 = ff1 @ W2 + b2  (split-K x2)
    tgemm<1,false,false><<<dim3(Ex/128, ROWS/128, 2), 256, GEMM_SMEM>>>(
        ff1, nullptr, 0, w2_t, b2, ff2, Ex, FFx, FFx/2, HALF_OUT);
    // 8) out = LN(attn_out + ff2A + ff2B)
    ln_add_kernel<<<ROWS, 128>>>(attnout, ff2, ff2 + (size_t)ROWS * Ex,
                                 ln2_g, ln2_b, out, nullptr);
}